// round 3
// baseline (speedup 1.0000x reference)
#include <cuda_runtime.h>

// YOLO decode, 3 scales fused. Block = 128 cells x 3 anchors = 384 threads.
// Each thread handles one (cell, anchor): 5 coalesced loads, 5 smem stores,
// then the block writes its contiguous 128*15-float output region as float4.

#define CPB 128          // cells per block
#define TPB (CPB * 3)    // 384 threads

__global__ __launch_bounds__(TPB) void detector_decode_kernel(
    const float* __restrict__ in13,
    const float* __restrict__ in26,
    const float* __restrict__ in52,
    const float* __restrict__ pthresh,
    float* __restrict__ out)
{
    __shared__ float s[CPB * 15];

    const int HW13 = 169, HW26 = 676, HW52 = 2704;
    const int N13 = 32 * HW13;   // 5408
    const int N26 = 32 * HW26;   // 21632
    const int N52 = 32 * HW52;   // 86528
    const int B13 = (N13 + CPB - 1) / CPB;   // 43
    const int B26 = (N26 + CPB - 1) / CPB;   // 169

    const int blk = blockIdx.x;
    const int tid = threadIdx.x;
    const int a  = tid >> 7;      // anchor lane 0..2
    const int ci = tid & 127;     // cell within block

    const float* __restrict__ in;
    int HW, W, N, cellBase;
    long outBase;
    float t, aw, ah;

    if (blk < B13) {
        in = in13; HW = HW13; W = 13; t = 32.0f; N = N13;
        cellBase = blk * CPB; outBase = 0;
        aw = (a == 0) ? 116.0f : (a == 1) ? 156.0f : 373.0f;
        ah = (a == 0) ?  90.0f : (a == 1) ? 198.0f : 326.0f;
    } else if (blk < B13 + B26) {
        in = in26; HW = HW26; W = 26; t = 16.0f; N = N26;
        cellBase = (blk - B13) * CPB; outBase = (long)N13 * 15;
        aw = (a == 0) ? 30.0f : (a == 1) ? 62.0f : 59.0f;
        ah = (a == 0) ? 61.0f : (a == 1) ? 45.0f : 119.0f;
    } else {
        in = in52; HW = HW52; W = 52; t = 8.0f; N = N52;
        cellBase = (blk - B13 - B26) * CPB; outBase = (long)(N13 + N26) * 15;
        aw = (a == 0) ? 10.0f : (a == 1) ? 16.0f : 33.0f;
        ah = (a == 0) ? 13.0f : (a == 1) ? 30.0f : 23.0f;
    }

    const float thresh = __ldg(pthresh);
    const int c = cellBase + ci;

    if (c < N) {
        const int b  = c / HW;
        const int hw = c - b * HW;
        const int h  = hw / W;
        const int w  = hw - h * W;

        // channel ch of anchor a at (b, h, w): b*255*HW + (a*85+ch)*HW + hw
        const float* __restrict__ p = in + (long)b * 255 * HW + (long)(a * 85) * HW + hw;

        // 5 independent coalesced loads in flight.
        const float conf = p[0];
        const float tx = p[HW];
        const float ty = p[2 * HW];
        const float tw = p[3 * HW];
        const float th = p[4 * HW];

        const bool m = conf > thresh;
        float* __restrict__ so = s + ci * 15 + a * 5;
        so[0] = m ? (float)b : 0.0f;
        so[1] = m ? ((float)w + tx) * t : 0.0f;
        so[2] = m ? ((float)h + ty) * t : 0.0f;
        so[3] = m ? aw * __expf(tw) : 0.0f;
        so[4] = m ? ah * __expf(th) : 0.0f;
    }

    __syncthreads();

    // Coalesced block write. Tail counts are multiples of 32 cells,
    // so totFloats is always a multiple of 4 -> float4 path exact.
    const int nvalid = min(CPB, N - cellBase);
    const int totFloats = nvalid * 15;
    float* __restrict__ dst = out + outBase + (long)cellBase * 15;

    float4* __restrict__ d4 = (float4*)dst;
    const float4* __restrict__ s4 = (const float4*)s;
    const int n4 = totFloats >> 2;
    for (int i = tid; i < n4; i += TPB) d4[i] = s4[i];
}

extern "C" void kernel_launch(void* const* d_in, const int* in_sizes, int n_in,
                              void* d_out, int out_size)
{
    const float* in13 = (const float*)d_in[0];
    const float* in26 = (const float*)d_in[1];
    const float* in52 = (const float*)d_in[2];
    const float* pthresh = (const float*)d_in[3];
    float* out = (float*)d_out;

    const int N13 = 32 * 169, N26 = 32 * 676, N52 = 32 * 2704;
    const int B13 = (N13 + CPB - 1) / CPB;   // 43
    const int B26 = (N26 + CPB - 1) / CPB;   // 169
    const int B52 = (N52 + CPB - 1) / CPB;   // 676
    detector_decode_kernel<<<B13 + B26 + B52, TPB>>>(in13, in26, in52, pthresh, out);
}